// round 6
// baseline (speedup 1.0000x reference)
#include <cuda_runtime.h>
#include <cuda_bf16.h>
#include <float.h>
#include <cstdint>

// Problem constants (fixed by the dataset)
#define MAX_NODES 100000
#define D_FEAT 32
#define D_HID 64
#define D_OUT 64
#define TILE_E 128

// Scratch: per-node precomputed terms.
// U[j] = x_j @ W1[:32] + pos_j @ W1[32:35] + b1   (N x 64)
// P[i] = pos_i @ W1[32:35]                        (N x 64)
// Per-edge preactivation = U[src] - P[dst].
__device__ float g_U[MAX_NODES * D_HID];
__device__ float g_P[MAX_NODES * D_HID];
__device__ int g_is64;

// ---------------------------------------------------------------------------
// PTX helpers (sm_80-era: ldmatrix + mma.sync — valid on plain sm_103 target)
// ---------------------------------------------------------------------------
__device__ __forceinline__ uint32_t smem_to_u32(const void* p) {
    uint32_t a;
    asm("{ .reg .u64 t; cvta.to.shared.u64 t, %1; cvt.u32.u64 %0, t; }"
        : "=r"(a) : "l"(p));
    return a;
}
__device__ __forceinline__ void ldm_x4(uint32_t* r, uint32_t addr) {
    asm volatile("ldmatrix.sync.aligned.m8n8.x4.shared.b16 {%0,%1,%2,%3}, [%4];"
                 : "=r"(r[0]), "=r"(r[1]), "=r"(r[2]), "=r"(r[3]) : "r"(addr));
}
__device__ __forceinline__ void ldm_x2(uint32_t& r0, uint32_t& r1, uint32_t addr) {
    asm volatile("ldmatrix.sync.aligned.m8n8.x2.shared.b16 {%0,%1}, [%2];"
                 : "=r"(r0), "=r"(r1) : "r"(addr));
}
__device__ __forceinline__ void mma_bf16(float* c, const uint32_t* a,
                                         uint32_t b0, uint32_t b1) {
    asm volatile(
        "mma.sync.aligned.m16n8k16.row.col.f32.bf16.bf16.f32 "
        "{%0,%1,%2,%3}, {%4,%5,%6,%7}, {%8,%9}, {%0,%1,%2,%3};"
        : "+f"(c[0]), "+f"(c[1]), "+f"(c[2]), "+f"(c[3])
        : "r"(a[0]), "r"(a[1]), "r"(a[2]), "r"(a[3]), "r"(b0), "r"(b1));
}

// SW128 swizzle for 128B rows: XOR bits[4:6] of the byte offset with (row&7).
#define SMEM_SWIZZLE_128B(off) ((off) ^ (((off) >> 3) & 0x70))

// ---------------------------------------------------------------------------
// Kernel 0: detect edge_index element width (int64 vs int32).
// ---------------------------------------------------------------------------
__global__ void detect_kernel(const long long* __restrict__ ei64, int E, int n) {
    __shared__ int bad;
    if (threadIdx.x == 0) bad = 0;
    __syncthreads();
    int samples = min(4096, E);
    for (int i = threadIdx.x; i < samples; i += blockDim.x) {
        long long v = ei64[i];
        if (v < 0 || v >= (long long)n) atomicOr(&bad, 1);
    }
    __syncthreads();
    if (threadIdx.x == 0) g_is64 = bad ? 0 : 1;
}

// ---------------------------------------------------------------------------
// Kernel 1: per-node precompute of U and P.
// ---------------------------------------------------------------------------
__global__ void precompute_kernel(const float* __restrict__ x,
                                  const float* __restrict__ pos,
                                  const float* __restrict__ W1,
                                  const float* __restrict__ b1,
                                  int n) {
    __shared__ float W1s[35 * 64];
    __shared__ float b1s[64];
    for (int i = threadIdx.x; i < 35 * 64; i += blockDim.x) W1s[i] = W1[i];
    if (threadIdx.x < 64) b1s[threadIdx.x] = b1[threadIdx.x];
    __syncthreads();

    int gid = blockIdx.x * blockDim.x + threadIdx.x;
    int node = gid >> 6;
    int k = gid & 63;
    if (node >= n) return;

    const float* xr = x + node * D_FEAT;
    float acc = b1s[k];
#pragma unroll
    for (int f = 0; f < D_FEAT; f++) acc = fmaf(xr[f], W1s[f * 64 + k], acc);
    float px = pos[node * 3 + 0];
    float py = pos[node * 3 + 1];
    float pz = pos[node * 3 + 2];
    float pp = px * W1s[32 * 64 + k];
    pp = fmaf(py, W1s[33 * 64 + k], pp);
    pp = fmaf(pz, W1s[34 * 64 + k], pp);

    g_U[node * 64 + k] = acc + pp;
    g_P[node * 64 + k] = pp;
}

// ---------------------------------------------------------------------------
// Kernel 2: init output to -FLT_MAX.
// ---------------------------------------------------------------------------
__global__ void init_out_kernel(float* __restrict__ out, int total) {
    int i = blockIdx.x * blockDim.x + threadIdx.x;
    if (i < total) out[i] = -FLT_MAX;
}

__device__ __forceinline__ void atomicMaxF(float* addr, float v) {
    if (v >= 0.0f) atomicMax((int*)addr, __float_as_int(v));
    else           atomicMin((unsigned int*)addr, __float_as_uint(v));
}

// ---------------------------------------------------------------------------
// SMEM layout (dynamic, 128B-aligned base)
// ---------------------------------------------------------------------------
#define OFF_AHI 0            // H hi: [128][64] bf16, 128B rows, SW128 = 16384
#define OFF_ALO 16384        // H lo: 16384
#define OFF_WHI 32768        // W^T hi: [64 n][64 k] bf16 = 8192
#define OFF_WLO 40960        // W^T lo: 8192
#define OFF_B2  49152        // 64 f32 = 256
#define OFF_DST 49408        // 128 int = 512
#define SMEM_BYTES 49920

// ---------------------------------------------------------------------------
// Kernel 3: HMMA edge kernel. 256 threads = 8 warps; block = 128-edge tile.
// Warp w owns edge rows [w*16, w*16+16). D = Ahi@Whi + Alo@Whi + Ahi@Wlo.
// ---------------------------------------------------------------------------
__global__ void __launch_bounds__(256, 2) edge_kernel(
    const void* __restrict__ ei_raw,
    const float* __restrict__ W2,       // [64 k][64 n]
    const float* __restrict__ b2,       // [64]
    float* __restrict__ out,            // [n, 64]
    int n, int E) {
    extern __shared__ __align__(128) char smem[];
    const uint32_t sb = smem_to_u32(smem);
    const int tid = threadIdx.x;
    const int wid = tid >> 5;
    const int lane = tid & 31;

    // ---- Stage W2^T hi/lo + bias ----
    for (int idx = tid; idx < 64 * 64; idx += 256) {
        int nn = idx >> 6;
        int kk = idx & 63;
        float w = W2[kk * 64 + nn];
        __nv_bfloat16 whi = __float2bfloat16_rn(w);
        __nv_bfloat16 wlo = __float2bfloat16_rn(w - __bfloat162float(whi));
        uint32_t sw = SMEM_SWIZZLE_128B((uint32_t)(nn * 128 + kk * 2));
        *(__nv_bfloat16*)(smem + OFF_WHI + sw) = whi;
        *(__nv_bfloat16*)(smem + OFF_WLO + sw) = wlo;
    }
    if (tid < 64) *(float*)(smem + OFF_B2 + tid * 4) = b2[tid];

    int* dsts = (int*)(smem + OFF_DST);
    const float* b2s = (const float*)(smem + OFF_B2);

    const int is64 = g_is64;
    const long long* ei64 = (const long long*)ei_raw;
    const int*       ei32 = (const int*)ei_raw;
    const int total = E + n;
    const int base = blockIdx.x * TILE_E;

    // ---- Stage H tile (gather + relu + bf16 hi/lo split) ----
    {
        const int c  = tid & 15;   // float4 chunk (cols c*4..c*4+3)
        const int es = tid >> 4;   // 16 edges per pass
#pragma unroll
        for (int j = 0; j < 8; j++) {
            int el = j * 16 + es;
            int eg = base + el;
            float4 h = make_float4(0.f, 0.f, 0.f, 0.f);
            long long d = -1;
            if (eg < total) {
                long long s;
                if (eg < E) {
                    if (is64) { s = ei64[eg]; d = ei64[E + eg]; }
                    else      { s = ei32[eg]; d = ei32[E + eg]; }
                } else { s = eg - E; d = s; }
                float4 u = *(const float4*)&g_U[s * 64 + c * 4];
                float4 p = *(const float4*)&g_P[d * 64 + c * 4];
                h.x = fmaxf(u.x - p.x, 0.0f);
                h.y = fmaxf(u.y - p.y, 0.0f);
                h.z = fmaxf(u.z - p.z, 0.0f);
                h.w = fmaxf(u.w - p.w, 0.0f);
            }
            if (c == 0) dsts[el] = (int)d;

            __nv_bfloat162 hi01, hi23, lo01, lo23;
            hi01.x = __float2bfloat16_rn(h.x);
            hi01.y = __float2bfloat16_rn(h.y);
            hi23.x = __float2bfloat16_rn(h.z);
            hi23.y = __float2bfloat16_rn(h.w);
            lo01.x = __float2bfloat16_rn(h.x - __bfloat162float(hi01.x));
            lo01.y = __float2bfloat16_rn(h.y - __bfloat162float(hi01.y));
            lo23.x = __float2bfloat16_rn(h.z - __bfloat162float(hi23.x));
            lo23.y = __float2bfloat16_rn(h.w - __bfloat162float(hi23.y));

            uint32_t sw = SMEM_SWIZZLE_128B((uint32_t)(el * 128 + c * 8));
            *(uint2*)(smem + OFF_AHI + sw) =
                make_uint2(*(uint32_t*)&hi01, *(uint32_t*)&hi23);
            *(uint2*)(smem + OFF_ALO + sw) =
                make_uint2(*(uint32_t*)&lo01, *(uint32_t*)&lo23);
        }
    }
    __syncthreads();

    // ---- GEMM: warp wid handles m-tile rows [wid*16, wid*16+16) ----
    const int m0 = wid * 16;
    const int r8   = lane & 7;
    const int bit1 = (lane >> 3) & 1;   // row +8 selector for A ldmatrix
    const int bit2 = (lane >> 4) & 1;   // col +8 selector for A ldmatrix

    // A ldmatrix lane address pieces. Swizzle XOR for these rows = (r8)<<4.
    const uint32_t aRow = (uint32_t)((m0 + r8 + 8 * bit1) * 128);
    uint32_t aColSwz[4];
#pragma unroll
    for (int ks = 0; ks < 4; ks++)
        aColSwz[ks] = (uint32_t)((16 * bit2 + 32 * ks) ^ (r8 << 4));

    // B ldmatrix (x2 uses lanes 0..15): rows n0+rB, col halves.
    const int lB = lane & 15;
    const int rB = lB & 7;
    const int bitB = (lB >> 3) & 1;
    const uint32_t bRowBase = (uint32_t)(rB * 128);
    uint32_t bColSwz[4];
#pragma unroll
    for (int ks = 0; ks < 4; ks++)
        bColSwz[ks] = (uint32_t)((16 * bitB + 32 * ks) ^ (rB << 4));

    uint32_t Ahi[4][4], Alo[4][4];
#pragma unroll
    for (int ks = 0; ks < 4; ks++) {
        ldm_x4(Ahi[ks], sb + OFF_AHI + aRow + aColSwz[ks]);
        ldm_x4(Alo[ks], sb + OFF_ALO + aRow + aColSwz[ks]);
    }

    float acc[8][4];
#pragma unroll
    for (int nt = 0; nt < 8; nt++)
#pragma unroll
        for (int q = 0; q < 4; q++) acc[nt][q] = 0.0f;

#pragma unroll
    for (int nt = 0; nt < 8; nt++) {
        const uint32_t bRow = bRowBase + (uint32_t)(nt * 8 * 128);
#pragma unroll
        for (int ks = 0; ks < 4; ks++) {
            uint32_t bh0, bh1, bl0, bl1;
            ldm_x2(bh0, bh1, sb + OFF_WHI + bRow + bColSwz[ks]);
            ldm_x2(bl0, bl1, sb + OFF_WLO + bRow + bColSwz[ks]);
            mma_bf16(acc[nt], Ahi[ks], bh0, bh1);
            mma_bf16(acc[nt], Alo[ks], bh0, bh1);
            mma_bf16(acc[nt], Ahi[ks], bl0, bl1);
        }
    }

    // ---- Epilogue: bias + pre-checked scatter-max ----
    const int g  = lane >> 2;       // 0..7
    const int t4 = lane & 3;        // 0..3
    const int dLo = dsts[m0 + g];
    const int dHi = dsts[m0 + g + 8];
    float* oLo = (dLo >= 0) ? out + (long long)dLo * 64 : nullptr;
    float* oHi = (dHi >= 0) ? out + (long long)dHi * 64 : nullptr;

#pragma unroll
    for (int nt = 0; nt < 8; nt++) {
        const int col = nt * 8 + t4 * 2;
        const float bias0 = b2s[col];
        const float bias1 = b2s[col + 1];
        if (oLo) {
            float v0 = acc[nt][0] + bias0;
            float v1 = acc[nt][1] + bias1;
            float2 cur = *(const float2*)(oLo + col);
            if (v0 > cur.x) atomicMaxF(oLo + col, v0);
            if (v1 > cur.y) atomicMaxF(oLo + col + 1, v1);
        }
        if (oHi) {
            float v2 = acc[nt][2] + bias0;
            float v3 = acc[nt][3] + bias1;
            float2 cur = *(const float2*)(oHi + col);
            if (v2 > cur.x) atomicMaxF(oHi + col, v2);
            if (v3 > cur.y) atomicMaxF(oHi + col + 1, v3);
        }
    }
}

// ---------------------------------------------------------------------------
// Launch
// ---------------------------------------------------------------------------
extern "C" void kernel_launch(void* const* d_in, const int* in_sizes, int n_in,
                              void* d_out, int out_size) {
    const float* x   = (const float*)d_in[0];    // [n, 32]
    const float* pos = (const float*)d_in[1];    // [n, 3]
    const void*  ei  = d_in[2];                  // [2, E] int64 or int32
    const float* W1  = (const float*)d_in[3];    // [35, 64]
    const float* b1  = (const float*)d_in[4];    // [64]
    const float* W2  = (const float*)d_in[5];    // [64, 64]
    const float* b2  = (const float*)d_in[6];    // [64]
    float*       out = (float*)d_out;            // [n, 64]

    int n = in_sizes[0] / D_FEAT;
    int E = in_sizes[2] / 2;

    cudaFuncSetAttribute(edge_kernel, cudaFuncAttributeMaxDynamicSharedMemorySize,
                         SMEM_BYTES);

    // 0) detect edge_index dtype
    detect_kernel<<<1, 256>>>((const long long*)ei, E, n);
    // 1) per-node precompute
    {
        int blocks = (n * 64 + 255) / 256;
        precompute_kernel<<<blocks, 256>>>(x, pos, W1, b1, n);
    }
    // 2) init output
    {
        int blocks = (n * 64 + 255) / 256;
        init_out_kernel<<<blocks, 256>>>(out, n * 64);
    }
    // 3) HMMA edge kernel
    {
        int total = E + n;
        int blocks = (total + TILE_E - 1) / TILE_E;
        edge_kernel<<<blocks, 256, SMEM_BYTES>>>(ei, W2, b2, out, n, E);
    }
}

// round 7
// speedup vs baseline: 1.3501x; 1.3501x over previous
#include <cuda_runtime.h>
#include <cuda_bf16.h>
#include <float.h>
#include <cstdint>

// Problem constants (fixed by the dataset)
#define MAX_NODES 100000
#define D_FEAT 32
#define D_HID 64
#define D_OUT 64

// Scratch: per-node precomputed terms.
// U[j] = x_j @ W1[:32] + pos_j @ W1[32:35] + b1   (N x 64)
// P[i] = pos_i @ W1[32:35]                        (N x 64)
// Per-edge preactivation = U[src] - P[dst].
__device__ float g_U[MAX_NODES * D_HID];
__device__ float g_P[MAX_NODES * D_HID];
__device__ int g_is64;

// ---------------------------------------------------------------------------
// mma.sync bf16 (sm_80-era PTX, valid on plain sm_103 target)
// ---------------------------------------------------------------------------
__device__ __forceinline__ void mma_bf16(float* c, const uint32_t* a,
                                         uint32_t b0, uint32_t b1) {
    asm volatile(
        "mma.sync.aligned.m16n8k16.row.col.f32.bf16.bf16.f32 "
        "{%0,%1,%2,%3}, {%4,%5,%6,%7}, {%8,%9}, {%0,%1,%2,%3};"
        : "+f"(c[0]), "+f"(c[1]), "+f"(c[2]), "+f"(c[3])
        : "r"(a[0]), "r"(a[1]), "r"(a[2]), "r"(a[3]), "r"(b0), "r"(b1));
}

// Pack hi parts (bf16 truncation) of two floats: low half = first arg.
__device__ __forceinline__ uint32_t pack_hi(float a, float b) {
    return __byte_perm(__float_as_uint(a), __float_as_uint(b), 0x7632);
}
// Residual after bf16 truncation (exact in fp32).
__device__ __forceinline__ float resid(float x) {
    return x - __uint_as_float(__float_as_uint(x) & 0xFFFF0000u);
}
__device__ __forceinline__ uint32_t pack_lo_rn(float a, float b) {
    __nv_bfloat162 t = __floats2bfloat162_rn(a, b);
    return *(uint32_t*)&t;
}

// ---------------------------------------------------------------------------
// Kernel 0: detect edge_index element width (int64 vs int32).
// ---------------------------------------------------------------------------
__global__ void detect_kernel(const long long* __restrict__ ei64, int E, int n) {
    __shared__ int bad;
    if (threadIdx.x == 0) bad = 0;
    __syncthreads();
    int samples = min(4096, E);
    for (int i = threadIdx.x; i < samples; i += blockDim.x) {
        long long v = ei64[i];
        if (v < 0 || v >= (long long)n) atomicOr(&bad, 1);
    }
    __syncthreads();
    if (threadIdx.x == 0) g_is64 = bad ? 0 : 1;
}

// ---------------------------------------------------------------------------
// Kernel 1: per-node precompute of U and P (grid-stride; W1 staged once/block).
// ---------------------------------------------------------------------------
__global__ void precompute_kernel(const float* __restrict__ x,
                                  const float* __restrict__ pos,
                                  const float* __restrict__ W1,
                                  const float* __restrict__ b1,
                                  int n) {
    __shared__ float W1s[35 * 64];
    __shared__ float b1s[64];
    for (int i = threadIdx.x; i < 35 * 64; i += blockDim.x) W1s[i] = W1[i];
    if (threadIdx.x < 64) b1s[threadIdx.x] = b1[threadIdx.x];
    __syncthreads();

    const int totalW = n * 64;
    for (int gid = blockIdx.x * blockDim.x + threadIdx.x; gid < totalW;
         gid += gridDim.x * blockDim.x) {
        int node = gid >> 6;
        int k = gid & 63;

        const float* xr = x + node * D_FEAT;
        float acc = b1s[k];
#pragma unroll
        for (int f = 0; f < D_FEAT; f++) acc = fmaf(xr[f], W1s[f * 64 + k], acc);
        float px = pos[node * 3 + 0];
        float py = pos[node * 3 + 1];
        float pz = pos[node * 3 + 2];
        float pp = px * W1s[32 * 64 + k];
        pp = fmaf(py, W1s[33 * 64 + k], pp);
        pp = fmaf(pz, W1s[34 * 64 + k], pp);

        g_U[node * 64 + k] = acc + pp;
        g_P[node * 64 + k] = pp;
    }
}

// ---------------------------------------------------------------------------
// Kernel 2: init output to -FLT_MAX (grid-stride).
// ---------------------------------------------------------------------------
__global__ void init_out_kernel(float* __restrict__ out, int total) {
    for (int i = blockIdx.x * blockDim.x + threadIdx.x; i < total;
         i += gridDim.x * blockDim.x)
        out[i] = -FLT_MAX;
}

__device__ __forceinline__ void atomicMaxF(float* addr, float v) {
    if (v >= 0.0f) atomicMax((int*)addr, __float_as_int(v));
    else           atomicMin((unsigned int*)addr, __float_as_uint(v));
}

// ---------------------------------------------------------------------------
// Kernel 3: persistent, sync-free HMMA edge kernel.
// Each warp PAIR owns 16-edge groups; within a pair, warp `half` handles
// output cols [half*32, half*32+32). W2 fragments (bf16 hi/lo) are built once
// per warp directly into registers. A fragments are gathered per group from
// g_U/g_P with float2 loads matching the m16n8k16 A layout; bf16 hi/lo split
// in registers. No shared memory, no block syncs.
// D = Ahi@Bhi + Alo@Bhi + Ahi@Blo   (error ~2^-17, rel_err ~1e-5)
// ---------------------------------------------------------------------------
__global__ void __launch_bounds__(256, 2) edge_kernel(
    const void* __restrict__ ei_raw,
    const float* __restrict__ W2,       // [64 k][64 n] row-major
    const float* __restrict__ b2,       // [64]
    float* __restrict__ out,            // [n, 64]
    int n, int E) {
    const int lane = threadIdx.x & 31;
    const int gwarp = (blockIdx.x * blockDim.x + threadIdx.x) >> 5;
    const int pairId = gwarp >> 1;
    const int half = gwarp & 1;
    const int n0 = half * 32;
    const int nPairs = (gridDim.x * blockDim.x) >> 6;

    const int tg = lane >> 2;   // fragment row group 0..7
    const int tk = lane & 3;    // thread in group

    // ---- Build persistent B fragments (W2^hi/lo) + bias ----
    uint32_t Bhi[4][4][2], Blo[4][4][2];
    float2 bias[4];
#pragma unroll
    for (int nt = 0; nt < 4; nt++) {
        const int colB = n0 + nt * 8 + tg;       // B frag n index
        const int colC = n0 + nt * 8 + tk * 2;   // C frag col base
        bias[nt] = *(const float2*)&b2[colC];
#pragma unroll
        for (int ks = 0; ks < 4; ks++) {
#pragma unroll
            for (int b = 0; b < 2; b++) {
                int k = ks * 16 + tk * 2 + b * 8;
                float w0 = W2[k * 64 + colB];
                float w1 = W2[(k + 1) * 64 + colB];
                Bhi[nt][ks][b] = pack_hi(w0, w1);
                Blo[nt][ks][b] = pack_lo_rn(resid(w0), resid(w1));
            }
        }
    }

    const int is64 = g_is64;
    const long long* ei64 = (const long long*)ei_raw;
    const int*       ei32 = (const int*)ei_raw;
    const int total = E + n;
    const int G = (total + 15) >> 4;

    for (int g = pairId; g < G; g += nPairs) {
        const int e0 = g * 16;
        // This thread's two edge rows: eA = e0+tg, eB = e0+tg+8
        int sA = 0, dA = -1, sB = 0, dB = -1;
        {
            int eA = e0 + tg;
            int eB = eA + 8;
            if (eA < E) {
                if (is64) { sA = (int)ei64[eA]; dA = (int)ei64[E + eA]; }
                else      { sA = ei32[eA];      dA = ei32[E + eA]; }
            } else if (eA < total) { sA = eA - E; dA = sA; }
            if (eB < E) {
                if (is64) { sB = (int)ei64[eB]; dB = (int)ei64[E + eB]; }
                else      { sB = ei32[eB];      dB = ei32[E + eB]; }
            } else if (eB < total) { sB = eB - E; dB = sB; }
        }
        const int sA_ = (dA >= 0) ? sA : 0;
        const int dA_ = (dA >= 0) ? dA : 0;
        const int sB_ = (dB >= 0) ? sB : 0;
        const int dB_ = (dB >= 0) ? dB : 0;

        const float* UA = g_U + sA_ * 64;
        const float* PA = g_P + dA_ * 64;
        const float* UB = g_U + sB_ * 64;
        const float* PB = g_P + dB_ * 64;

        float acc[4][4];
#pragma unroll
        for (int nt = 0; nt < 4; nt++)
#pragma unroll
            for (int q = 0; q < 4; q++) acc[nt][q] = 0.0f;

#pragma unroll
        for (int ks = 0; ks < 4; ks++) {
            const int k2 = ks * 16 + tk * 2;
            // a0: (eA, k2..k2+1)  a1: (eB, k2..)  a2: (eA, k2+8..)  a3: (eB, k2+8..)
            float2 uA0 = *(const float2*)&UA[k2];
            float2 pA0 = *(const float2*)&PA[k2];
            float2 uB0 = *(const float2*)&UB[k2];
            float2 pB0 = *(const float2*)&PB[k2];
            float2 uA8 = *(const float2*)&UA[k2 + 8];
            float2 pA8 = *(const float2*)&PA[k2 + 8];
            float2 uB8 = *(const float2*)&UB[k2 + 8];
            float2 pB8 = *(const float2*)&PB[k2 + 8];

            float hA0x = fmaxf(uA0.x - pA0.x, 0.0f), hA0y = fmaxf(uA0.y - pA0.y, 0.0f);
            float hB0x = fmaxf(uB0.x - pB0.x, 0.0f), hB0y = fmaxf(uB0.y - pB0.y, 0.0f);
            float hA8x = fmaxf(uA8.x - pA8.x, 0.0f), hA8y = fmaxf(uA8.y - pA8.y, 0.0f);
            float hB8x = fmaxf(uB8.x - pB8.x, 0.0f), hB8y = fmaxf(uB8.y - pB8.y, 0.0f);

            uint32_t Ahi[4], Alo[4];
            Ahi[0] = pack_hi(hA0x, hA0y);
            Ahi[1] = pack_hi(hB0x, hB0y);
            Ahi[2] = pack_hi(hA8x, hA8y);
            Ahi[3] = pack_hi(hB8x, hB8y);
            Alo[0] = pack_lo_rn(resid(hA0x), resid(hA0y));
            Alo[1] = pack_lo_rn(resid(hB0x), resid(hB0y));
            Alo[2] = pack_lo_rn(resid(hA8x), resid(hA8y));
            Alo[3] = pack_lo_rn(resid(hB8x), resid(hB8y));

#pragma unroll
            for (int nt = 0; nt < 4; nt++) {
                mma_bf16(acc[nt], Ahi, Bhi[nt][ks][0], Bhi[nt][ks][1]);
                mma_bf16(acc[nt], Alo, Bhi[nt][ks][0], Bhi[nt][ks][1]);
                mma_bf16(acc[nt], Ahi, Blo[nt][ks][0], Blo[nt][ks][1]);
            }
        }

        // ---- Epilogue: bias + pre-checked scatter-max ----
        if (dA >= 0) {
            float* o = out + dA * 64 + n0 + tk * 2;
#pragma unroll
            for (int nt = 0; nt < 4; nt++) {
                float v0 = acc[nt][0] + bias[nt].x;
                float v1 = acc[nt][1] + bias[nt].y;
                float2 cur = *(const float2*)(o + nt * 8);
                if (v0 > cur.x) atomicMaxF(o + nt * 8, v0);
                if (v1 > cur.y) atomicMaxF(o + nt * 8 + 1, v1);
            }
        }
        if (dB >= 0) {
            float* o = out + dB * 64 + n0 + tk * 2;
#pragma unroll
            for (int nt = 0; nt < 4; nt++) {
                float v2 = acc[nt][2] + bias[nt].x;
                float v3 = acc[nt][3] + bias[nt].y;
                float2 cur = *(const float2*)(o + nt * 8);
                if (v2 > cur.x) atomicMaxF(o + nt * 8, v2);
                if (v3 > cur.y) atomicMaxF(o + nt * 8 + 1, v3);
            }
        }
    }
}

// ---------------------------------------------------------------------------
// Launch
// ---------------------------------------------------------------------------
extern "C" void kernel_launch(void* const* d_in, const int* in_sizes, int n_in,
                              void* d_out, int out_size) {
    const float* x   = (const float*)d_in[0];    // [n, 32]
    const float* pos = (const float*)d_in[1];    // [n, 3]
    const void*  ei  = d_in[2];                  // [2, E] int64 or int32
    const float* W1  = (const float*)d_in[3];    // [35, 64]
    const float* b1  = (const float*)d_in[4];    // [64]
    const float* W2  = (const float*)d_in[5];    // [64, 64]
    const float* b2  = (const float*)d_in[6];    // [64]
    float*       out = (float*)d_out;            // [n, 64]

    int n = in_sizes[0] / D_FEAT;
    int E = in_sizes[2] / 2;

    // 0) detect edge_index dtype
    detect_kernel<<<1, 256>>>((const long long*)ei, E, n);
    // 1) per-node precompute (grid-stride)
    precompute_kernel<<<1480, 256>>>(x, pos, W1, b1, n);
    // 2) init output (grid-stride)
    init_out_kernel<<<1480, 256>>>(out, n * 64);
    // 3) persistent sync-free HMMA edge kernel (2 CTAs/SM)
    edge_kernel<<<296, 256>>>(ei, W2, b2, out, n, E);
}